// round 2
// baseline (speedup 1.0000x reference)
#include <cuda_runtime.h>
#include <cstdint>

// Problem constants (fixed by the dataset)
constexpr int B_ = 4;
constexpr int L_ = 4096;
constexpr int D_ = 1024;
constexpr int H_ = 16;
constexpr int M_ = 64;
constexpr int BL = B_ * L_;   // 16384
constexpr int HM = H_ * M_;   // 1024
constexpr float EPS = 0.001f;

// Scratch (no allocations allowed -> __device__ globals)
__device__ float g_q[BL * HM];
__device__ float g_k[BL * HM];
__device__ float g_v[BL * HM];
__device__ float g_attn[BL * HM];
__device__ float g_kvs[B_ * H_ * M_ * M_];   // [b][h][m][d]
__device__ float g_ksum[B_ * H_ * M_];       // [b][h][m]

// ---------------------------------------------------------------------------
// SGEMM: C[M,N] = A[M,K] * B[K,N] + bias[N], optional (relu + EPS) epilogue.
// Classic 128x128 tile, BK=8, 256 threads, 8x8 per-thread micro-tile.
// All dims are multiples of 128/8 here, so no bounds checks.
// ---------------------------------------------------------------------------
template <bool RELU>
__global__ __launch_bounds__(256)
void sgemm_kernel(const float* __restrict__ A, const float* __restrict__ Bm,
                  const float* __restrict__ bias, float* __restrict__ C,
                  int M, int N, int K) {
    constexpr int BM = 128, BN = 128, BK = 8, TM = 8, TN = 8;
    __shared__ float As[BK][BM];
    __shared__ float Bs[BK][BN];

    const int tid = threadIdx.x;
    const int bx = blockIdx.x;   // N tile
    const int by = blockIdx.y;   // M tile

    // A tile loader: 128 rows x 8 cols = 256 float4 (2 per row)
    const int a_row = tid >> 1;
    const int a_col = (tid & 1) << 2;
    // B tile loader: 8 rows x 128 cols = 256 float4
    const int b_row = tid >> 5;
    const int b_col = (tid & 31) << 2;

    const int ty = tid >> 4;     // 0..15
    const int tx = tid & 15;     // 0..15

    const float* Ap = A + (size_t)(by * BM) * K;
    const float* Bp = Bm + bx * BN;

    float acc[TM][TN];
#pragma unroll
    for (int i = 0; i < TM; i++)
#pragma unroll
        for (int j = 0; j < TN; j++) acc[i][j] = 0.f;

    for (int k0 = 0; k0 < K; k0 += BK) {
        float4 av = *(const float4*)(Ap + (size_t)a_row * K + k0 + a_col);
        As[a_col + 0][a_row] = av.x;
        As[a_col + 1][a_row] = av.y;
        As[a_col + 2][a_row] = av.z;
        As[a_col + 3][a_row] = av.w;
        float4 bv = *(const float4*)(Bp + (size_t)(k0 + b_row) * N + b_col);
        *(float4*)&Bs[b_row][b_col] = bv;
        __syncthreads();

#pragma unroll
        for (int kk = 0; kk < BK; kk++) {
            float af[TM], bf[TN];
#pragma unroll
            for (int i = 0; i < TM; i++) af[i] = As[kk][ty * TM + i];
#pragma unroll
            for (int j = 0; j < TN; j++) bf[j] = Bs[kk][tx * TN + j];
#pragma unroll
            for (int i = 0; i < TM; i++)
#pragma unroll
                for (int j = 0; j < TN; j++) acc[i][j] += af[i] * bf[j];
        }
        __syncthreads();
    }

    // Epilogue: bias (+ optional relu+EPS), vectorized stores
#pragma unroll
    for (int i = 0; i < TM; i++) {
        const int row = by * BM + ty * TM + i;
        float* Cp = C + (size_t)row * N + bx * BN + tx * TN;
        const float* bp = bias + bx * BN + tx * TN;
#pragma unroll
        for (int j = 0; j < TN; j += 4) {
            float4 v;
            v.x = acc[i][j + 0] + bp[j + 0];
            v.y = acc[i][j + 1] + bp[j + 1];
            v.z = acc[i][j + 2] + bp[j + 2];
            v.w = acc[i][j + 3] + bp[j + 3];
            if (RELU) {
                v.x = fmaxf(v.x, 0.f) + EPS;
                v.y = fmaxf(v.y, 0.f) + EPS;
                v.z = fmaxf(v.z, 0.f) + EPS;
                v.w = fmaxf(v.w, 0.f) + EPS;
            }
            *(float4*)(Cp + j) = v;
        }
    }
}

// ---------------------------------------------------------------------------
// KV state: kvs[b,h,m,d] = sum_l k[b,l,h,m] * v[b,l,h,d]; ksum[b,h,m] = sum_l k.
// Grid (B*H, NSPLIT), 256 threads. Each thread owns a 4x4 patch of the 64x64
// state; L is split across blocks and merged with atomics (state pre-zeroed).
// ---------------------------------------------------------------------------
constexpr int NSPLIT = 8;
constexpr int LT = 16;

__global__ __launch_bounds__(256)
void kv_state_kernel(const float* __restrict__ k, const float* __restrict__ v) {
    const int bh = blockIdx.x;
    const int b = bh >> 4, h = bh & 15;
    const int l0 = blockIdx.y * (L_ / NSPLIT);
    const int tid = threadIdx.x;

    __shared__ float ks[LT][M_];
    __shared__ float vs[LT][M_];

    const int lrow = tid >> 4;          // 0..15
    const int lcol = (tid & 15) << 2;   // 0..60
    const int ti = tid >> 4;            // m base = ti*4
    const int tj = tid & 15;            // d base = tj*4

    const float* kb = k + (size_t)(b * L_) * HM + h * M_;
    const float* vb = v + (size_t)(b * L_) * HM + h * M_;

    float acc[4][4];
#pragma unroll
    for (int i = 0; i < 4; i++)
#pragma unroll
        for (int j = 0; j < 4; j++) acc[i][j] = 0.f;
    float ksacc = 0.f;

    for (int l = l0; l < l0 + L_ / NSPLIT; l += LT) {
        *(float4*)&ks[lrow][lcol] = *(const float4*)(kb + (size_t)(l + lrow) * HM + lcol);
        *(float4*)&vs[lrow][lcol] = *(const float4*)(vb + (size_t)(l + lrow) * HM + lcol);
        __syncthreads();
#pragma unroll
        for (int ll = 0; ll < LT; ll++) {
            float kf[4], vf[4];
#pragma unroll
            for (int i = 0; i < 4; i++) kf[i] = ks[ll][ti * 4 + i];
#pragma unroll
            for (int j = 0; j < 4; j++) vf[j] = vs[ll][tj * 4 + j];
#pragma unroll
            for (int i = 0; i < 4; i++)
#pragma unroll
                for (int j = 0; j < 4; j++) acc[i][j] += kf[i] * vf[j];
        }
        if (tid < M_) {
#pragma unroll
            for (int ll = 0; ll < LT; ll++) ksacc += ks[ll][tid];
        }
        __syncthreads();
    }

    float* kvp = g_kvs + (size_t)bh * M_ * M_;
#pragma unroll
    for (int i = 0; i < 4; i++)
#pragma unroll
        for (int j = 0; j < 4; j++)
            atomicAdd(&kvp[(ti * 4 + i) * M_ + tj * 4 + j], acc[i][j]);
    if (tid < M_) atomicAdd(&g_ksum[bh * M_ + tid], ksacc);
}

// ---------------------------------------------------------------------------
// Apply: attn[b,l,h,d] = (sum_m q[b,l,h,m]*kvs[b,h,m,d]) / (sum_m q*ksum).
// Grid (B*H, L/64), 256 threads = 4 rows x 64 cols. kvs tile cached in smem.
// ---------------------------------------------------------------------------
constexpr int LROWS = 64;

__global__ __launch_bounds__(256)
void attn_apply_kernel(const float* __restrict__ q) {
    const int bh = blockIdx.x;
    const int b = bh >> 4, h = bh & 15;
    const int tid = threadIdx.x;

    __shared__ float skvs[M_ * M_];
    __shared__ float sks[M_];
    __shared__ float sq[4][M_];

    const float* kvp = g_kvs + (size_t)bh * M_ * M_;
    for (int i = tid; i < (M_ * M_) / 4; i += 256)
        ((float4*)skvs)[i] = ((const float4*)kvp)[i];
    if (tid < M_) sks[tid] = g_ksum[bh * M_ + tid];
    __syncthreads();

    const int lr = tid >> 6;    // 0..3
    const int m = tid & 63;     // output d index
    const int lbase = blockIdx.y * LROWS;
    const float* qb = q + (size_t)(b * L_) * HM + h * M_;
    float* ab = g_attn + (size_t)(b * L_) * HM + h * M_;

    for (int l = lbase + lr; l < lbase + LROWS; l += 4) {
        sq[lr][m] = qb[(size_t)l * HM + m];
        __syncthreads();
        float acc = 0.f, nrm = 0.f;
#pragma unroll
        for (int j = 0; j < M_; j++) {
            const float qv = sq[lr][j];
            acc += qv * skvs[j * M_ + m];
            nrm += qv * sks[j];
        }
        ab[(size_t)l * HM + m] = acc / nrm;
        __syncthreads();
    }
}

// ---------------------------------------------------------------------------
// Launch
// ---------------------------------------------------------------------------
extern "C" void kernel_launch(void* const* d_in, const int* in_sizes, int n_in,
                              void* d_out, int out_size) {
    (void)in_sizes; (void)n_in; (void)out_size;
    const float* query = (const float*)d_in[0];
    const float* key_  = (const float*)d_in[1];
    const float* value = (const float*)d_in[2];
    const float* Wq = (const float*)d_in[3];
    const float* bq = (const float*)d_in[4];
    const float* Wk = (const float*)d_in[5];
    const float* bk = (const float*)d_in[6];
    const float* Wv = (const float*)d_in[7];
    const float* bv = (const float*)d_in[8];
    const float* Wo = (const float*)d_in[9];
    const float* bo = (const float*)d_in[10];
    float* out = (float*)d_out;

    float *qp = nullptr, *kp = nullptr, *vp = nullptr, *ap = nullptr;
    float *kvsp = nullptr, *ksump = nullptr;
    cudaGetSymbolAddress((void**)&qp, g_q);
    cudaGetSymbolAddress((void**)&kp, g_k);
    cudaGetSymbolAddress((void**)&vp, g_v);
    cudaGetSymbolAddress((void**)&ap, g_attn);
    cudaGetSymbolAddress((void**)&kvsp, g_kvs);
    cudaGetSymbolAddress((void**)&ksump, g_ksum);

    cudaMemsetAsync(kvsp, 0, sizeof(float) * B_ * H_ * M_ * M_);
    cudaMemsetAsync(ksump, 0, sizeof(float) * B_ * H_ * M_);

    dim3 blk(256);
    dim3 gproj(HM / 128, BL / 128);
    // Q/K projections with relu+EPS epilogue; V plain
    sgemm_kernel<true ><<<gproj, blk>>>(query, Wq, bq, qp, BL, HM, D_);
    sgemm_kernel<true ><<<gproj, blk>>>(key_,  Wk, bk, kp, BL, HM, D_);
    sgemm_kernel<false><<<gproj, blk>>>(value, Wv, bv, vp, BL, HM, D_);

    kv_state_kernel<<<dim3(B_ * H_, NSPLIT), blk>>>(kp, vp);
    attn_apply_kernel<<<dim3(B_ * H_, L_ / LROWS), blk>>>(qp);

    // Output projection: attn [BL, HM] x Wo [HM, D] + bo
    sgemm_kernel<false><<<dim3(D_ / 128, BL / 128), blk>>>(ap, Wo, bo, out, BL, D_, HM);
}

// round 3
// speedup vs baseline: 2.1664x; 2.1664x over previous
#include <cuda_runtime.h>
#include <cuda_bf16.h>
#include <cstdint>

// Problem constants (fixed by the dataset)
constexpr int B_ = 4;
constexpr int L_ = 4096;
constexpr int D_ = 1024;
constexpr int H_ = 16;
constexpr int M_ = 64;
constexpr int BL = B_ * L_;   // 16384
constexpr int HM = H_ * M_;   // 1024
constexpr float EPS = 0.001f;

typedef unsigned short u16;
typedef unsigned int u32;

// ---------------------------------------------------------------------------
// Scratch (__device__ globals; no allocations allowed)
// ---------------------------------------------------------------------------
// fp32 intermediates for the attention core
__device__ float g_q[BL * HM];
__device__ float g_k[BL * HM];
__device__ float g_v[BL * HM];
__device__ float g_kvs[B_ * H_ * M_ * M_];
__device__ float g_ksum[B_ * H_ * M_];
// bf16 hi/lo splits of GEMM A-operands (activations)
__device__ u16 g_qa_h[BL * D_], g_qa_l[BL * D_];
__device__ u16 g_ka_h[BL * D_], g_ka_l[BL * D_];
__device__ u16 g_va_h[BL * D_], g_va_l[BL * D_];
__device__ u16 g_at_h[BL * HM], g_at_l[BL * HM];
// bf16 hi/lo splits of weights, pre-transposed to [N][K]
__device__ u16 g_wq_h[HM * D_], g_wq_l[HM * D_];
__device__ u16 g_wk_h[HM * D_], g_wk_l[HM * D_];
__device__ u16 g_wv_h[HM * D_], g_wv_l[HM * D_];
__device__ u16 g_wo_h[D_ * HM], g_wo_l[D_ * HM];

// ---------------------------------------------------------------------------
// Split helpers
// ---------------------------------------------------------------------------
__device__ __forceinline__ void split_bf16(float x, u16& hi, u16& lo) {
    __nv_bfloat16 h = __float2bfloat16(x);
    hi = __bfloat16_as_ushort(h);
    lo = __bfloat16_as_ushort(__float2bfloat16(x - __bfloat162float(h)));
}

// fp32 [n] -> bf16 hi/lo [n], contiguous, vectorized
__global__ __launch_bounds__(256)
void split_convert_kernel(const float* __restrict__ in, u16* __restrict__ hi,
                          u16* __restrict__ lo, int n) {
    int i = (blockIdx.x * 256 + threadIdx.x) * 4;
    if (i >= n) return;
    float4 v = *(const float4*)(in + i);
    ushort4 h, l;
    split_bf16(v.x, h.x, l.x);
    split_bf16(v.y, h.y, l.y);
    split_bf16(v.z, h.z, l.z);
    split_bf16(v.w, h.w, l.w);
    *(ushort4*)(hi + i) = h;
    *(ushort4*)(lo + i) = l;
}

// fp32 in[Kd][Nd] -> bf16 hi/lo out[Nd][Kd] (transposed)
__global__ __launch_bounds__(256)
void transpose_split_kernel(const float* __restrict__ in, u16* __restrict__ oh,
                            u16* __restrict__ ol, int Kd, int Nd) {
    __shared__ float t[32][33];
    const int n0 = blockIdx.x * 32, k0 = blockIdx.y * 32;
    const int tx = threadIdx.x & 31, ty = threadIdx.x >> 5;  // 32 x 8
    for (int r = ty; r < 32; r += 8)
        t[r][tx] = in[(size_t)(k0 + r) * Nd + n0 + tx];
    __syncthreads();
    for (int r = ty; r < 32; r += 8) {
        float x = t[tx][r];
        u16 h, l;
        split_bf16(x, h, l);
        size_t o = (size_t)(n0 + r) * Kd + k0 + tx;
        oh[o] = h;
        ol[o] = l;
    }
}

// ---------------------------------------------------------------------------
// Split-bf16 tensor-core GEMM:
//   C[M,N] = A[M,K] * B[K,N] + bias[N]  (optional relu+EPS)
//   A given as bf16 hi/lo [M][K]; B given PRE-TRANSPOSED bf16 hi/lo [N][K].
//   C ~= Ahi*Bhi + Alo*Bhi + Ahi*Blo  (fp32 accum)
// 128x128x32 tiles, 256 threads (8 warps as 4x2, warp tile 32x64),
// mma.sync.m16n8k16, cp.async double buffer.
// ---------------------------------------------------------------------------
constexpr int AW = 20;           // smem words per row: 16 payload + 4 pad
constexpr int TW = 128 * AW;     // words per tile array (2560 = 10KB)
constexpr int GEMM_SMEM = 2 * 4 * TW * 4;  // 81920 B

__device__ __forceinline__ void mma_bf16(float* c, const u32* a, const u32* b) {
    asm volatile(
        "mma.sync.aligned.m16n8k16.row.col.f32.bf16.bf16.f32 "
        "{%0,%1,%2,%3},{%4,%5,%6,%7},{%8,%9},{%0,%1,%2,%3};"
        : "+f"(c[0]), "+f"(c[1]), "+f"(c[2]), "+f"(c[3])
        : "r"(a[0]), "r"(a[1]), "r"(a[2]), "r"(a[3]), "r"(b[0]), "r"(b[1]));
}

__device__ __forceinline__ void cp16(u32 smem_addr, const void* gptr) {
    asm volatile("cp.async.cg.shared.global [%0], [%1], 16;\n" ::"r"(smem_addr),
                 "l"(gptr));
}

template <bool RELU>
__global__ __launch_bounds__(256, 1)
void gemm_split(const u16* __restrict__ Ah, const u16* __restrict__ Al,
                const u16* __restrict__ Bh, const u16* __restrict__ Bl,
                const float* __restrict__ bias, float* __restrict__ C,
                int Nd, int Kd) {
    extern __shared__ u32 sm[];
    const int tid = threadIdx.x, lane = tid & 31, warp = tid >> 5;
    const int wm = warp >> 1, wn = warp & 1;
    const int g = lane >> 2, tig = lane & 3;
    const int bm = blockIdx.y * 128, bn = blockIdx.x * 128;

    const u16* srcs[4] = {Ah, Al, Bh, Bl};

    float acc[2][8][4];
#pragma unroll
    for (int mf = 0; mf < 2; mf++)
#pragma unroll
        for (int nf = 0; nf < 8; nf++)
#pragma unroll
            for (int i = 0; i < 4; i++) acc[mf][nf][i] = 0.f;

    const int NIT = Kd / 32;

    // stage loader: 4 arrays x 512 16B-chunks
    auto load_stage = [&](int s, int k0) {
#pragma unroll
        for (int arr = 0; arr < 4; arr++) {
            const u16* src = srcs[arr];
            const int rbase = (arr < 2) ? bm : bn;
            u32* dst = sm + (s * 4 + arr) * TW;
#pragma unroll
            for (int c = tid; c < 512; c += 256) {
                int r = c >> 2, p = c & 3;
                const u16* gp = src + (size_t)(rbase + r) * Kd + k0 + p * 8;
                u32 da = (u32)__cvta_generic_to_shared(dst + r * AW + p * 4);
                cp16(da, gp);
            }
        }
        asm volatile("cp.async.commit_group;\n" ::);
    };

    load_stage(0, 0);

#pragma unroll 1
    for (int it = 0; it < NIT; it++) {
        if (it + 1 < NIT) {
            load_stage((it + 1) & 1, (it + 1) * 32);
            asm volatile("cp.async.wait_group 1;\n" ::);
        } else {
            asm volatile("cp.async.wait_group 0;\n" ::);
        }
        __syncthreads();

        const int s = it & 1;
        const u32* Ah_s = sm + (s * 4 + 0) * TW;
        const u32* Al_s = sm + (s * 4 + 1) * TW;
        const u32* Bh_s = sm + (s * 4 + 2) * TW;
        const u32* Bl_s = sm + (s * 4 + 3) * TW;

#pragma unroll
        for (int ks = 0; ks < 2; ks++) {
            const int ko = ks * 8;
            u32 a_h[2][4], a_l[2][4], bb[8][2];
#pragma unroll
            for (int mf = 0; mf < 2; mf++) {
                const int r0 = wm * 32 + mf * 16 + g;
                a_h[mf][0] = Ah_s[r0 * AW + ko + tig];
                a_h[mf][1] = Ah_s[(r0 + 8) * AW + ko + tig];
                a_h[mf][2] = Ah_s[r0 * AW + ko + 4 + tig];
                a_h[mf][3] = Ah_s[(r0 + 8) * AW + ko + 4 + tig];
            }
#pragma unroll
            for (int nf = 0; nf < 8; nf++) {
                const int n = wn * 64 + nf * 8 + g;
                bb[nf][0] = Bh_s[n * AW + ko + tig];
                bb[nf][1] = Bh_s[n * AW + ko + 4 + tig];
            }
            // hi * hi
#pragma unroll
            for (int mf = 0; mf < 2; mf++)
#pragma unroll
                for (int nf = 0; nf < 8; nf++) mma_bf16(acc[mf][nf], a_h[mf], bb[nf]);
            // lo * hi
#pragma unroll
            for (int mf = 0; mf < 2; mf++) {
                const int r0 = wm * 32 + mf * 16 + g;
                a_l[mf][0] = Al_s[r0 * AW + ko + tig];
                a_l[mf][1] = Al_s[(r0 + 8) * AW + ko + tig];
                a_l[mf][2] = Al_s[r0 * AW + ko + 4 + tig];
                a_l[mf][3] = Al_s[(r0 + 8) * AW + ko + 4 + tig];
            }
#pragma unroll
            for (int mf = 0; mf < 2; mf++)
#pragma unroll
                for (int nf = 0; nf < 8; nf++) mma_bf16(acc[mf][nf], a_l[mf], bb[nf]);
            // hi * lo
#pragma unroll
            for (int nf = 0; nf < 8; nf++) {
                const int n = wn * 64 + nf * 8 + g;
                bb[nf][0] = Bl_s[n * AW + ko + tig];
                bb[nf][1] = Bl_s[n * AW + ko + 4 + tig];
            }
#pragma unroll
            for (int mf = 0; mf < 2; mf++)
#pragma unroll
                for (int nf = 0; nf < 8; nf++) mma_bf16(acc[mf][nf], a_h[mf], bb[nf]);
        }
        __syncthreads();
    }

    // Epilogue
#pragma unroll
    for (int mf = 0; mf < 2; mf++) {
#pragma unroll
        for (int nf = 0; nf < 8; nf++) {
            const int row0 = bm + wm * 32 + mf * 16 + g;
            const int col = bn + wn * 64 + nf * 8 + 2 * tig;
            const float bx = bias[col], by = bias[col + 1];
            float2 v0, v1;
            v0.x = acc[mf][nf][0] + bx;
            v0.y = acc[mf][nf][1] + by;
            v1.x = acc[mf][nf][2] + bx;
            v1.y = acc[mf][nf][3] + by;
            if (RELU) {
                v0.x = fmaxf(v0.x, 0.f) + EPS;
                v0.y = fmaxf(v0.y, 0.f) + EPS;
                v1.x = fmaxf(v1.x, 0.f) + EPS;
                v1.y = fmaxf(v1.y, 0.f) + EPS;
            }
            *(float2*)(C + (size_t)row0 * Nd + col) = v0;
            *(float2*)(C + (size_t)(row0 + 8) * Nd + col) = v1;
        }
    }
}

// ---------------------------------------------------------------------------
// KV state: kvs[b,h,m,d] = sum_l k[b,l,h,m]*v[b,l,h,d]; ksum = sum_l k. (fp32)
// ---------------------------------------------------------------------------
constexpr int NSPLIT = 8;
constexpr int LT = 16;

__global__ __launch_bounds__(256)
void kv_state_kernel(const float* __restrict__ k, const float* __restrict__ v) {
    const int bh = blockIdx.x;
    const int b = bh >> 4, h = bh & 15;
    const int l0 = blockIdx.y * (L_ / NSPLIT);
    const int tid = threadIdx.x;

    __shared__ float ks[LT][M_];
    __shared__ float vs[LT][M_];

    const int lrow = tid >> 4;
    const int lcol = (tid & 15) << 2;
    const int ti = tid >> 4;
    const int tj = tid & 15;

    const float* kb = k + (size_t)(b * L_) * HM + h * M_;
    const float* vb = v + (size_t)(b * L_) * HM + h * M_;

    float acc[4][4];
#pragma unroll
    for (int i = 0; i < 4; i++)
#pragma unroll
        for (int j = 0; j < 4; j++) acc[i][j] = 0.f;
    float ksacc = 0.f;

    for (int l = l0; l < l0 + L_ / NSPLIT; l += LT) {
        *(float4*)&ks[lrow][lcol] = *(const float4*)(kb + (size_t)(l + lrow) * HM + lcol);
        *(float4*)&vs[lrow][lcol] = *(const float4*)(vb + (size_t)(l + lrow) * HM + lcol);
        __syncthreads();
#pragma unroll
        for (int ll = 0; ll < LT; ll++) {
            float kf[4], vf[4];
#pragma unroll
            for (int i = 0; i < 4; i++) kf[i] = ks[ll][ti * 4 + i];
#pragma unroll
            for (int j = 0; j < 4; j++) vf[j] = vs[ll][tj * 4 + j];
#pragma unroll
            for (int i = 0; i < 4; i++)
#pragma unroll
                for (int j = 0; j < 4; j++) acc[i][j] += kf[i] * vf[j];
        }
        if (tid < M_) {
#pragma unroll
            for (int ll = 0; ll < LT; ll++) ksacc += ks[ll][tid];
        }
        __syncthreads();
    }

    float* kvp = g_kvs + (size_t)bh * M_ * M_;
#pragma unroll
    for (int i = 0; i < 4; i++)
#pragma unroll
        for (int j = 0; j < 4; j++)
            atomicAdd(&kvp[(ti * 4 + i) * M_ + tj * 4 + j], acc[i][j]);
    if (tid < M_) atomicAdd(&g_ksum[bh * M_ + tid], ksacc);
}

// ---------------------------------------------------------------------------
// Apply: attn = (q . kvs) / (q . ksum); emits bf16 hi/lo split for out-proj.
// ---------------------------------------------------------------------------
constexpr int LROWS = 64;

__global__ __launch_bounds__(256)
void attn_apply_kernel(const float* __restrict__ q) {
    const int bh = blockIdx.x;
    const int b = bh >> 4, h = bh & 15;
    const int tid = threadIdx.x;

    __shared__ float skvs[M_ * M_];
    __shared__ float sks[M_];
    __shared__ float sq[4][M_];

    const float* kvp = g_kvs + (size_t)bh * M_ * M_;
    for (int i = tid; i < (M_ * M_) / 4; i += 256)
        ((float4*)skvs)[i] = ((const float4*)kvp)[i];
    if (tid < M_) sks[tid] = g_ksum[bh * M_ + tid];
    __syncthreads();

    const int lr = tid >> 6;
    const int m = tid & 63;
    const int lbase = blockIdx.y * LROWS;
    const float* qb = q + (size_t)(b * L_) * HM + h * M_;
    u16* ah = g_at_h + (size_t)(b * L_) * HM + h * M_;
    u16* al = g_at_l + (size_t)(b * L_) * HM + h * M_;

    for (int l = lbase + lr; l < lbase + LROWS; l += 4) {
        sq[lr][m] = qb[(size_t)l * HM + m];
        __syncthreads();
        float acc = 0.f, nrm = 0.f;
#pragma unroll
        for (int j = 0; j < M_; j++) {
            const float qv = sq[lr][j];
            acc += qv * skvs[j * M_ + m];
            nrm += qv * sks[j];
        }
        const float r = acc / nrm;
        u16 hh, ll;
        split_bf16(r, hh, ll);
        ah[(size_t)l * HM + m] = hh;
        al[(size_t)l * HM + m] = ll;
        __syncthreads();
    }
}

// ---------------------------------------------------------------------------
// Launch
// ---------------------------------------------------------------------------
extern "C" void kernel_launch(void* const* d_in, const int* in_sizes, int n_in,
                              void* d_out, int out_size) {
    (void)in_sizes; (void)n_in; (void)out_size;
    const float* query = (const float*)d_in[0];
    const float* key_  = (const float*)d_in[1];
    const float* value = (const float*)d_in[2];
    const float* Wq = (const float*)d_in[3];
    const float* bq = (const float*)d_in[4];
    const float* Wk = (const float*)d_in[5];
    const float* bk = (const float*)d_in[6];
    const float* Wv = (const float*)d_in[7];
    const float* bv = (const float*)d_in[8];
    const float* Wo = (const float*)d_in[9];
    const float* bo = (const float*)d_in[10];
    float* out = (float*)d_out;

    float *qp, *kp, *vp, *kvsp, *ksump;
    cudaGetSymbolAddress((void**)&qp, g_q);
    cudaGetSymbolAddress((void**)&kp, g_k);
    cudaGetSymbolAddress((void**)&vp, g_v);
    cudaGetSymbolAddress((void**)&kvsp, g_kvs);
    cudaGetSymbolAddress((void**)&ksump, g_ksum);

    u16 *qa_h, *qa_l, *ka_h, *ka_l, *va_h, *va_l, *at_h, *at_l;
    u16 *wq_h, *wq_l, *wk_h, *wk_l, *wv_h, *wv_l, *wo_h, *wo_l;
    cudaGetSymbolAddress((void**)&qa_h, g_qa_h);
    cudaGetSymbolAddress((void**)&qa_l, g_qa_l);
    cudaGetSymbolAddress((void**)&ka_h, g_ka_h);
    cudaGetSymbolAddress((void**)&ka_l, g_ka_l);
    cudaGetSymbolAddress((void**)&va_h, g_va_h);
    cudaGetSymbolAddress((void**)&va_l, g_va_l);
    cudaGetSymbolAddress((void**)&at_h, g_at_h);
    cudaGetSymbolAddress((void**)&at_l, g_at_l);
    cudaGetSymbolAddress((void**)&wq_h, g_wq_h);
    cudaGetSymbolAddress((void**)&wq_l, g_wq_l);
    cudaGetSymbolAddress((void**)&wk_h, g_wk_h);
    cudaGetSymbolAddress((void**)&wk_l, g_wk_l);
    cudaGetSymbolAddress((void**)&wv_h, g_wv_h);
    cudaGetSymbolAddress((void**)&wv_l, g_wv_l);
    cudaGetSymbolAddress((void**)&wo_h, g_wo_h);
    cudaGetSymbolAddress((void**)&wo_l, g_wo_l);

    cudaFuncSetAttribute(gemm_split<true>,
                         cudaFuncAttributeMaxDynamicSharedMemorySize, GEMM_SMEM);
    cudaFuncSetAttribute(gemm_split<false>,
                         cudaFuncAttributeMaxDynamicSharedMemorySize, GEMM_SMEM);

    cudaMemsetAsync(kvsp, 0, sizeof(float) * B_ * H_ * M_ * M_);
    cudaMemsetAsync(ksump, 0, sizeof(float) * B_ * H_ * M_);

    // Input conversions
    const int nact = BL * D_;
    split_convert_kernel<<<nact / 4 / 256, 256>>>(query, qa_h, qa_l, nact);
    split_convert_kernel<<<nact / 4 / 256, 256>>>(key_,  ka_h, ka_l, nact);
    split_convert_kernel<<<nact / 4 / 256, 256>>>(value, va_h, va_l, nact);
    // Weight transposes ([K][N] -> [N][K])
    transpose_split_kernel<<<dim3(32, 32), 256>>>(Wq, wq_h, wq_l, D_, HM);
    transpose_split_kernel<<<dim3(32, 32), 256>>>(Wk, wk_h, wk_l, D_, HM);
    transpose_split_kernel<<<dim3(32, 32), 256>>>(Wv, wv_h, wv_l, D_, HM);
    transpose_split_kernel<<<dim3(32, 32), 256>>>(Wo, wo_h, wo_l, HM, D_);

    // Projections (tensor core, split-bf16)
    dim3 blk(256);
    dim3 gproj(HM / 128, BL / 128);
    gemm_split<true ><<<gproj, blk, GEMM_SMEM>>>(qa_h, qa_l, wq_h, wq_l, bq, qp, HM, D_);
    gemm_split<true ><<<gproj, blk, GEMM_SMEM>>>(ka_h, ka_l, wk_h, wk_l, bk, kp, HM, D_);
    gemm_split<false><<<gproj, blk, GEMM_SMEM>>>(va_h, va_l, wv_h, wv_l, bv, vp, HM, D_);

    // Linear attention core (fp32)
    kv_state_kernel<<<dim3(B_ * H_, NSPLIT), blk>>>(kp, vp);
    attn_apply_kernel<<<dim3(B_ * H_, L_ / LROWS), blk>>>(qp);

    // Output projection
    gemm_split<false><<<dim3(D_ / 128, BL / 128), blk, GEMM_SMEM>>>(
        at_h, at_l, wo_h, wo_l, bo, out, D_, HM);
}